// round 11
// baseline (speedup 1.0000x reference)
#include <cuda_runtime.h>
#include <cstdint>

// P: [N=12, T=4096, D=2048] fp32; subgroup_indices: [2,6] (int32 or int64);
// out: [1, T, 2*D] fp32 ; out[t, s*D+d] = max_{g<6} P[idx[s*6+g], t, d]
//
// ROOFLINE STATUS (closed): 470 MB irreducible traffic. Four kernel shapes
// (occ 63-87%, MLP 6-12, 256/512 threads, cache hints on/off) all pin DRAM
// at 84-85% of 8 TB/s spec (6.7 TB/s) — the B300-achievable ceiling for this
// 12-read-stream + 1-write-stream mix. This is the converged best shape:
// one thread per (t,d4) column producing both subgroup outputs; 12
// independent LDG.128 (issued in two 6-load batches with interleaved
// reduction to cut live registers); 2 coalesced STG.128; vectorized index
// load; zero decode math on the load path (col == linear thread id).

#define T_FRAMES   4096
#define D_DIM      2048
#define D4         (D_DIM / 4)            // 512 float4 per (n,t) row
#define COLS       (T_FRAMES * D4)        // 2,097,152 columns
#define TD4        ((long long)T_FRAMES * D4)
#define THREADS    256

__device__ __forceinline__ float4 f4max(float4 a, float4 b) {
    a.x = fmaxf(a.x, b.x);
    a.y = fmaxf(a.y, b.y);
    a.z = fmaxf(a.z, b.z);
    a.w = fmaxf(a.w, b.w);
    return a;
}

__global__ __launch_bounds__(THREADS) void subgroup_maxpool_kernel(
    const float4* __restrict__ P4,
    const int4*   __restrict__ idx_v,    // index buffer viewed as int4 words
    float4*       __restrict__ out4)
{
    const int i = blockIdx.x * THREADS + threadIdx.x;
    if (i >= COLS) return;

    // Read the index buffer with vector loads.
    // int64 arange -> words 0,0,1,0,2,0,... ; int32 arange -> 0,1,2,...
    const int4 w0 = __ldg(&idx_v[0]);
    const int4 w1 = __ldg(&idx_v[1]);
    const int4 w2 = __ldg(&idx_v[2]);
    const bool is64 = (w0.y == 0);

    int n[12];
    if (is64) {
        n[0] = w0.x;  n[1] = w0.z;  n[2] = w1.x;  n[3] = w1.z;
        n[4] = w2.x;  n[5] = w2.z;
        const int4 w3 = __ldg(&idx_v[3]);
        const int4 w4 = __ldg(&idx_v[4]);
        const int4 w5 = __ldg(&idx_v[5]);
        n[6] = w3.x;  n[7] = w3.z;  n[8] = w4.x;  n[9] = w4.z;
        n[10] = w5.x; n[11] = w5.z;
    } else {
        n[0] = w0.x;  n[1] = w0.y;  n[2] = w0.z;  n[3] = w0.w;
        n[4] = w1.x;  n[5] = w1.y;  n[6] = w1.z;  n[7] = w1.w;
        n[8] = w2.x;  n[9] = w2.y;  n[10] = w2.z; n[11] = w2.w;
    }

    const long long col = i;   // col == t*D4 + d4 by construction

    // Batch 1: subgroup 0's six loads, then reduce (frees 5 float4 regs
    // before batch 2's loads need them).
    float4 a0 = __ldcs(P4 + (long long)n[0] * TD4 + col);
    float4 a1 = __ldcs(P4 + (long long)n[1] * TD4 + col);
    float4 a2 = __ldcs(P4 + (long long)n[2] * TD4 + col);
    float4 a3 = __ldcs(P4 + (long long)n[3] * TD4 + col);
    float4 a4 = __ldcs(P4 + (long long)n[4] * TD4 + col);
    float4 a5 = __ldcs(P4 + (long long)n[5] * TD4 + col);

    // Batch 2: subgroup 1's six loads issued before consuming batch 1.
    float4 b0 = __ldcs(P4 + (long long)n[6]  * TD4 + col);
    float4 b1 = __ldcs(P4 + (long long)n[7]  * TD4 + col);
    float4 b2 = __ldcs(P4 + (long long)n[8]  * TD4 + col);
    float4 b3 = __ldcs(P4 + (long long)n[9]  * TD4 + col);
    float4 b4 = __ldcs(P4 + (long long)n[10] * TD4 + col);
    float4 b5 = __ldcs(P4 + (long long)n[11] * TD4 + col);

    const float4 m0 = f4max(f4max(f4max(a0, a1), f4max(a2, a3)), f4max(a4, a5));
    const float4 m1 = f4max(f4max(f4max(b0, b1), f4max(b2, b3)), f4max(b4, b5));

    // out index: t*1024 + s*512 + d4, with t = i>>9, d4 = i&511.
    const int t  = i >> 9;
    const int d4 = i & (D4 - 1);
    const int o  = (t << 10) | d4;
    __stcs(&out4[o], m0);
    __stcs(&out4[o + D4], m1);
}

extern "C" void kernel_launch(void* const* d_in, const int* in_sizes, int n_in,
                              void* d_out, int out_size)
{
    const float4* P4  = (const float4*)d_in[0];
    const int4*   idx = (const int4*)d_in[1];
    float4*       out = (float4*)d_out;

    const int blocks = (COLS + THREADS - 1) / THREADS;  // 8192
    subgroup_maxpool_kernel<<<blocks, THREADS>>>(P4, idx, out);
}